// round 2
// baseline (speedup 1.0000x reference)
#include <cuda_runtime.h>
#include <math_constants.h>
#include <cstdint>

// Fused attention: scores = (x1 @ x2^T) / x3 ; softmax ; JAX-threefry dropout(p=0.5, key 42,
// PARTITIONABLE threefry: bits[g] = x0^x1 of threefry2x32((0,42), (0, g)));
// out = probs_dropped @ x1 + x2.   B=2, H=16, S=2048, D=128, fp32.
//
// Grid: (S/BM, B*H) = (16, 32). Block: 256 threads (tx=16, ty=16).

#define S_LEN 2048
#define D_DIM 128
#define BM 128
#define BN 64
#define NT 256

// smem strides (floats). All strides multiple of 4 for aligned float4 access.
#define QS_STRIDE 132
#define KS_STRIDE 68
#define VS_STRIDE 128
#define PS_STRIDE 132

#define QS_OFF 0
#define KS_OFF (QS_OFF + D_DIM * QS_STRIDE)   // 128*132 = 16896
#define VS_OFF (KS_OFF + D_DIM * KS_STRIDE)   // +128*68 = 8704
#define PS_OFF (VS_OFF + BN * VS_STRIDE)      // +64*128 = 8192
#define SMEM_FLOATS (PS_OFF + BN * PS_STRIDE) // +64*132 = 8448 -> 42240 floats
#define SMEM_BYTES (SMEM_FLOATS * 4)          // 168960 B

__device__ __forceinline__ unsigned tf_rotl(unsigned x, int r) {
    return __funnelshift_l(x, x, r);
}

// JAX threefry2x32, key = (0, 42), PARTITIONABLE counter scheme (default since
// JAX 0.4.36): for 32-bit draws at global linear index g (size 2^27 < 2^32 so
// hi=0): (o0,o1) = threefry2x32((0,42), (0, g)); bits = o0 ^ o1.
// uniform u = ((bits>>9)|0x3f800000) - 1 ;  keep = (u < 0.5) <=> MSB(bits)==0.
__device__ __forceinline__ unsigned threefry_bits_part(unsigned g) {
    const unsigned ks0 = 0u;
    const unsigned ks1 = 42u;
    const unsigned ks2 = 0x1BD11BDAu ^ 42u;
    unsigned x0 = 0u + ks0;         // counter hi word = 0
    unsigned x1 = g + ks1;          // counter lo word = g
#define TF_ROUND(r) { x0 += x1; x1 = tf_rotl(x1, (r)) ^ x0; }
    TF_ROUND(13) TF_ROUND(15) TF_ROUND(26) TF_ROUND(6)
    x0 += ks1; x1 += ks2 + 1u;
    TF_ROUND(17) TF_ROUND(29) TF_ROUND(16) TF_ROUND(24)
    x0 += ks2; x1 += ks0 + 2u;
    TF_ROUND(13) TF_ROUND(15) TF_ROUND(26) TF_ROUND(6)
    x0 += ks0; x1 += ks1 + 3u;
    TF_ROUND(17) TF_ROUND(29) TF_ROUND(16) TF_ROUND(24)
    x0 += ks1; x1 += ks2 + 4u;
    TF_ROUND(13) TF_ROUND(15) TF_ROUND(26) TF_ROUND(6)
    x0 += ks2; x1 += ks0 + 5u;
#undef TF_ROUND
    return x0 ^ x1;
}

__global__ void __launch_bounds__(NT, 1)
attn_fused_kernel(const float* __restrict__ x1,
                  const float* __restrict__ x2,
                  const float* __restrict__ x3,
                  float* __restrict__ out)
{
    extern __shared__ float sm[];
    float* QsT = sm + QS_OFF;   // [D][BM]  (transposed Q)
    float* KsT = sm + KS_OFF;   // [D][BN]  (transposed K tile)
    float* Vs  = sm + VS_OFF;   // [BN][D]  (natural V tile)
    float* PsT = sm + PS_OFF;   // [BN][BM] (masked P transposed)

    const int tid = threadIdx.x;
    const int tx  = tid & 15;
    const int ty  = tid >> 4;
    const int bh  = blockIdx.y;           // 0..31 = b*16 + h
    const int q0  = blockIdx.x * BM;

    const float* Q = x1 + (size_t)bh * (S_LEN * D_DIM);
    const float* K = x2 + (size_t)bh * (S_LEN * D_DIM);
    const float* V = Q;                    // values are x1
    const float* R = K;                    // residual is x2
    float* O = out + (size_t)bh * (S_LEN * D_DIM);
    const float inv3 = 1.0f / x3[bh];

    // ---- load Q tile transposed: QsT[d][r] = Q[q0+r][d] ----
    #pragma unroll
    for (int it = 0; it < 16; ++it) {
        int idx = tid + it * NT;          // 0..4095 float4s
        int r   = idx & 127;
        int c4  = idx >> 7;
        float4 v = *reinterpret_cast<const float4*>(Q + (size_t)(q0 + r) * D_DIM + c4 * 4);
        QsT[(c4 * 4 + 0) * QS_STRIDE + r] = v.x;
        QsT[(c4 * 4 + 1) * QS_STRIDE + r] = v.y;
        QsT[(c4 * 4 + 2) * QS_STRIDE + r] = v.z;
        QsT[(c4 * 4 + 3) * QS_STRIDE + r] = v.w;
    }

    float o[8][8];
    float m[8], l[8];
    #pragma unroll
    for (int i = 0; i < 8; ++i) {
        m[i] = -CUDART_INF_F;
        l[i] = 0.0f;
        #pragma unroll
        for (int j = 0; j < 8; ++j) o[i][j] = 0.0f;
    }

    // Global dropout linear index base (includes batch via bh):
    // g = (bh*2048 + q)*2048 + k ;  bh<32, q<2048, k<2048 -> g < 2^27.
    const unsigned trow = ((unsigned)bh * 2048u + (unsigned)(q0 + ty * 8)) * 2048u
                          + (unsigned)(tx * 4);

    for (int kt = 0; kt < S_LEN / BN; ++kt) {
        const int k0 = kt * BN;
        __syncthreads();   // previous iter's PsT/Vs/KsT consumers are done

        // ---- load K tile transposed (KsT[d][c]) and V tile natural (Vs[c][d]) ----
        #pragma unroll
        for (int it = 0; it < 8; ++it) {
            int idx = tid + it * NT;       // 0..2047 float4s
            int rk  = idx & 63;
            int ck4 = idx >> 6;
            float4 kv = *reinterpret_cast<const float4*>(K + (size_t)(k0 + rk) * D_DIM + ck4 * 4);
            KsT[(ck4 * 4 + 0) * KS_STRIDE + rk] = kv.x;
            KsT[(ck4 * 4 + 1) * KS_STRIDE + rk] = kv.y;
            KsT[(ck4 * 4 + 2) * KS_STRIDE + rk] = kv.z;
            KsT[(ck4 * 4 + 3) * KS_STRIDE + rk] = kv.w;
            int rv  = idx >> 5;
            int cv4 = idx & 31;
            float4 vv = *reinterpret_cast<const float4*>(V + (size_t)(k0 + rv) * D_DIM + cv4 * 4);
            *reinterpret_cast<float4*>(Vs + rv * VS_STRIDE + cv4 * 4) = vv;
        }
        __syncthreads();

        // ---- S tile = Q @ K^T : thread micro-tile 8 rows x 4 cols ----
        float s[8][4];
        #pragma unroll
        for (int i = 0; i < 8; ++i)
            #pragma unroll
            for (int c = 0; c < 4; ++c) s[i][c] = 0.0f;

        #pragma unroll 4
        for (int d = 0; d < D_DIM; ++d) {
            float4 a0 = *reinterpret_cast<const float4*>(QsT + d * QS_STRIDE + ty * 8);
            float4 a1 = *reinterpret_cast<const float4*>(QsT + d * QS_STRIDE + ty * 8 + 4);
            float4 bb = *reinterpret_cast<const float4*>(KsT + d * KS_STRIDE + tx * 4);
            float a[8] = {a0.x, a0.y, a0.z, a0.w, a1.x, a1.y, a1.z, a1.w};
            float bv[4] = {bb.x, bb.y, bb.z, bb.w};
            #pragma unroll
            for (int i = 0; i < 8; ++i)
                #pragma unroll
                for (int c = 0; c < 4; ++c)
                    s[i][c] = fmaf(a[i], bv[c], s[i][c]);
        }

        #pragma unroll
        for (int i = 0; i < 8; ++i)
            #pragma unroll
            for (int c = 0; c < 4; ++c) s[i][c] *= inv3;

        // ---- online softmax (denominator WITHOUT dropout; dropout is post-softmax) ----
        #pragma unroll
        for (int i = 0; i < 8; ++i) {
            float mx = fmaxf(fmaxf(s[i][0], s[i][1]), fmaxf(s[i][2], s[i][3]));
            mx = fmaxf(mx, __shfl_xor_sync(0xffffffffu, mx, 8));
            mx = fmaxf(mx, __shfl_xor_sync(0xffffffffu, mx, 4));
            mx = fmaxf(mx, __shfl_xor_sync(0xffffffffu, mx, 2));
            mx = fmaxf(mx, __shfl_xor_sync(0xffffffffu, mx, 1));
            float mn = fmaxf(m[i], mx);
            float sc = __expf(m[i] - mn);     // first tile: exp(-inf) = 0
            m[i] = mn;
            float rs = 0.0f;
            #pragma unroll
            for (int c = 0; c < 4; ++c) {
                float p = __expf(s[i][c] - mn);
                s[i][c] = p;
                rs += p;
            }
            rs += __shfl_xor_sync(0xffffffffu, rs, 8);
            rs += __shfl_xor_sync(0xffffffffu, rs, 4);
            rs += __shfl_xor_sync(0xffffffffu, rs, 2);
            rs += __shfl_xor_sync(0xffffffffu, rs, 1);
            l[i] = l[i] * sc + rs;
            #pragma unroll
            for (int j = 0; j < 8; ++j) o[i][j] *= sc;
        }

        // ---- threefry dropout mask (partitionable) + stage masked P^T ----
        const unsigned tcol = trow + (unsigned)k0;
        #pragma unroll
        for (int c = 0; c < 4; ++c) {
            float pm[8];
            #pragma unroll
            for (int i = 0; i < 8; ++i) {
                unsigned bits = threefry_bits_part(tcol + (unsigned)(i * 2048) + (unsigned)c);
                pm[i] = ((int)bits >= 0) ? s[i][c] : 0.0f;   // keep iff MSB==0
            }
            float4* dst = reinterpret_cast<float4*>(PsT + (tx * 4 + c) * PS_STRIDE + ty * 8);
            dst[0] = make_float4(pm[0], pm[1], pm[2], pm[3]);
            dst[1] = make_float4(pm[4], pm[5], pm[6], pm[7]);
        }
        __syncthreads();

        // ---- accumulate O += P_masked @ V : thread micro-tile 8 x 8 ----
        #pragma unroll 2
        for (int kk = 0; kk < BN; ++kk) {
            float4 a0 = *reinterpret_cast<const float4*>(PsT + kk * PS_STRIDE + ty * 8);
            float4 a1 = *reinterpret_cast<const float4*>(PsT + kk * PS_STRIDE + ty * 8 + 4);
            float4 b0 = *reinterpret_cast<const float4*>(Vs + kk * VS_STRIDE + tx * 8);
            float4 b1 = *reinterpret_cast<const float4*>(Vs + kk * VS_STRIDE + tx * 8 + 4);
            float a[8]  = {a0.x, a0.y, a0.z, a0.w, a1.x, a1.y, a1.z, a1.w};
            float bv[8] = {b0.x, b0.y, b0.z, b0.w, b1.x, b1.y, b1.z, b1.w};
            #pragma unroll
            for (int i = 0; i < 8; ++i)
                #pragma unroll
                for (int j = 0; j < 8; ++j)
                    o[i][j] = fmaf(a[i], bv[j], o[i][j]);
        }
    }

    // ---- epilogue: out = 2 * o / l + residual(x2) ----
    #pragma unroll
    for (int i = 0; i < 8; ++i) {
        float invl = 2.0f / l[i];           // 1/(1-p) = 2 folded here
        size_t row = (size_t)(q0 + ty * 8 + i);
        const float4* res = reinterpret_cast<const float4*>(R + row * D_DIM + tx * 8);
        float4 r0 = res[0];
        float4 r1 = res[1];
        float4 w0, w1;
        w0.x = fmaf(o[i][0], invl, r0.x);
        w0.y = fmaf(o[i][1], invl, r0.y);
        w0.z = fmaf(o[i][2], invl, r0.z);
        w0.w = fmaf(o[i][3], invl, r0.w);
        w1.x = fmaf(o[i][4], invl, r1.x);
        w1.y = fmaf(o[i][5], invl, r1.y);
        w1.z = fmaf(o[i][6], invl, r1.z);
        w1.w = fmaf(o[i][7], invl, r1.w);
        float4* dstp = reinterpret_cast<float4*>(O + row * D_DIM + tx * 8);
        dstp[0] = w0;
        dstp[1] = w1;
    }
}

extern "C" void kernel_launch(void* const* d_in, const int* in_sizes, int n_in,
                              void* d_out, int out_size) {
    const float* x1 = (const float*)d_in[0];   // [2,16,2048,128]
    const float* x2 = (const float*)d_in[1];   // [2,16,2048,128]
    const float* x3 = (const float*)d_in[2];   // [2,16,1,1] -> 32 floats
    float* out = (float*)d_out;                // [2,16,2048,128]

    (void)in_sizes; (void)n_in; (void)out_size;

    cudaFuncSetAttribute(attn_fused_kernel,
                         cudaFuncAttributeMaxDynamicSharedMemorySize, SMEM_BYTES);

    dim3 grid(S_LEN / BM, 32);   // (16 q-tiles, B*H heads)
    attn_fused_kernel<<<grid, NT, SMEM_BYTES>>>(x1, x2, x3, out);
}

// round 3
// speedup vs baseline: 2.6346x; 2.6346x over previous
#include <cuda_runtime.h>
#include <cuda_fp16.h>
#include <math_constants.h>
#include <cstdint>

// Fused attention via mma.sync (HMMA fp16, fp32 acc):
//   scores = (x1 @ x2^T)/x3 ; softmax ; JAX partitionable-threefry dropout(p=.5, key 42);
//   out = probs_dropped @ x1 + x2.   B=2,H=16,S=2048,D=128 fp32.
// Precision: S-GEMM uses fp16 hi/lo split (3 MMAs: qh*kh + qh*kl + ql*kh).
// PV GEMM plain fp16 (P in [0,1], V=x1). Expected rel_err ~3e-4.
//
// Grid (16, 32), block 256 (8 warps x 16 rows). BN=64 K-tile.

#define S_LEN 2048
#define D_DIM 128
#define BM 128
#define BN 64
#define NT 256

#define KST 136                      // halves per smem row (128 + 8 pad) = 272 B
#define KH_OFF 0
#define KL_OFF (64 * KST)            // halves
#define VH_OFF (2 * 64 * KST)
#define SMEM_HALVES (3 * 64 * KST)
#define SMEM_BYTES (SMEM_HALVES * 2) // 52224 B

__device__ __forceinline__ unsigned tf_rotl(unsigned x, int r) {
    return __funnelshift_l(x, x, r);
}

// JAX threefry2x32, key=(0,42), partitionable: bits(g) = x0^x1 of
// threefry2x32((0,42),(0,g)). keep iff MSB==0 (u < 0.5).
__device__ __forceinline__ unsigned threefry_bits_part(unsigned g) {
    const unsigned ks1 = 42u;
    const unsigned ks2 = 0x1BD11BDAu ^ 42u;
    unsigned x0 = 0u;
    unsigned x1 = g + ks1;
#define TF_ROUND(r) { x0 += x1; x1 = tf_rotl(x1, (r)) ^ x0; }
    TF_ROUND(13) TF_ROUND(15) TF_ROUND(26) TF_ROUND(6)
    x0 += ks1; x1 += ks2 + 1u;
    TF_ROUND(17) TF_ROUND(29) TF_ROUND(16) TF_ROUND(24)
    x0 += ks2; x1 += 0u + 2u;
    TF_ROUND(13) TF_ROUND(15) TF_ROUND(26) TF_ROUND(6)
    x0 += 0u; x1 += ks1 + 3u;
    TF_ROUND(17) TF_ROUND(29) TF_ROUND(16) TF_ROUND(24)
    x0 += ks1; x1 += ks2 + 4u;
    TF_ROUND(13) TF_ROUND(15) TF_ROUND(26) TF_ROUND(6)
    x0 += ks2; x1 += 0u + 5u;
#undef TF_ROUND
    return x0 ^ x1;
}

__device__ __forceinline__ uint32_t packh2(__half a, __half b) {
    __half2 h = __halves2half2(a, b);
    return *reinterpret_cast<uint32_t*>(&h);
}

__device__ __forceinline__ void mma_f16(float c[4], const uint32_t a[4],
                                        uint32_t b0, uint32_t b1) {
    asm volatile(
        "mma.sync.aligned.m16n8k16.row.col.f32.f16.f16.f32 "
        "{%0,%1,%2,%3}, {%4,%5,%6,%7}, {%8,%9}, {%0,%1,%2,%3};\n"
        : "+f"(c[0]), "+f"(c[1]), "+f"(c[2]), "+f"(c[3])
        : "r"(a[0]), "r"(a[1]), "r"(a[2]), "r"(a[3]), "r"(b0), "r"(b1));
}

__device__ __forceinline__ void ldsm_x4(uint32_t& r0, uint32_t& r1,
                                        uint32_t& r2, uint32_t& r3, uint32_t addr) {
    asm volatile("ldmatrix.sync.aligned.m8n8.x4.shared.b16 {%0,%1,%2,%3}, [%4];"
                 : "=r"(r0), "=r"(r1), "=r"(r2), "=r"(r3) : "r"(addr));
}

__device__ __forceinline__ void ldsm_x4_t(uint32_t& r0, uint32_t& r1,
                                          uint32_t& r2, uint32_t& r3, uint32_t addr) {
    asm volatile("ldmatrix.sync.aligned.m8n8.x4.trans.shared.b16 {%0,%1,%2,%3}, [%4];"
                 : "=r"(r0), "=r"(r1), "=r"(r2), "=r"(r3) : "r"(addr));
}

__global__ void __launch_bounds__(NT, 1)
attn_mma_kernel(const float* __restrict__ x1,
                const float* __restrict__ x2,
                const float* __restrict__ x3,
                float* __restrict__ out)
{
    extern __shared__ __half smh[];
    __half* Kh = smh + KH_OFF;
    __half* Kl = smh + KL_OFF;
    __half* Vh = smh + VH_OFF;

    const int tid  = threadIdx.x;
    const int warp = tid >> 5;
    const int lane = tid & 31;
    const int g    = lane >> 2;   // 0..7 (fragment row group)
    const int c    = lane & 3;    // 0..3 (fragment col pair)
    const int bh   = blockIdx.y;  // 0..31 = b*16 + h
    const int q0   = blockIdx.x * BM;
    const int qrow = q0 + warp * 16 + g;

    const float* Q  = x1 + (size_t)bh * (S_LEN * D_DIM);
    const float* Kg = x2 + (size_t)bh * (S_LEN * D_DIM);
    const float* Vg = Q;                 // values are x1
    const float* R  = Kg;                // residual is x2
    float* O = out + (size_t)bh * (S_LEN * D_DIM);
    const float inv3 = 1.0f / x3[bh];

    // ---- Q fragments resident (hi + lo split), 8 k-tiles of 16 ----
    uint32_t qh[8][4], ql[8][4];
    #pragma unroll
    for (int t = 0; t < 8; ++t) {
        #pragma unroll
        for (int p = 0; p < 4; ++p) {
            int row = qrow + (p & 1) * 8;
            int col = 16 * t + (p >> 1) * 8 + 2 * c;
            float2 v = *reinterpret_cast<const float2*>(Q + (size_t)row * D_DIM + col);
            __half hx = __float2half_rn(v.x), hy = __float2half_rn(v.y);
            __half lx = __float2half_rn(v.x - __half2float(hx));
            __half ly = __float2half_rn(v.y - __half2float(hy));
            qh[t][p] = packh2(hx, hy);
            ql[t][p] = packh2(lx, ly);
        }
    }

    // ---- accumulators ----
    float oacc[16][4];
    #pragma unroll
    for (int i = 0; i < 16; ++i)
        #pragma unroll
        for (int j = 0; j < 4; ++j) oacc[i][j] = 0.0f;
    float m0 = -CUDART_INF_F, m1 = -CUDART_INF_F;
    float l0 = 0.0f, l1 = 0.0f;

    // ldmatrix per-lane address components
    const uint32_t smem_u32 = (uint32_t)__cvta_generic_to_shared(smh);
    const int lr  = lane & 7;
    const int seg = lane >> 3;
    const uint32_t k_lane_off = (uint32_t)(lr * 272 + ((seg & 1) * 8 + (seg >> 1) * 16) * 2);
    const uint32_t v_lane_off = (uint32_t)(((seg & 1) * 8 + lr) * 272 + ((seg >> 1) * 8) * 2);
    const uint32_t kh_base = smem_u32 + k_lane_off;
    const uint32_t kl_base = smem_u32 + (uint32_t)(KL_OFF * 2) + k_lane_off;
    const uint32_t vh_base = smem_u32 + (uint32_t)(VH_OFF * 2) + v_lane_off;

    // dropout index base: g_idx = (bh*2048 + row)*2048 + col
    const unsigned gbase = ((unsigned)bh * 2048u + (unsigned)qrow) * 2048u + (unsigned)(2 * c);

    for (int kt = 0; kt < S_LEN / BN; ++kt) {
        const int k0 = kt * BN;
        __syncthreads();

        // ---- stage K (hi+lo) and V (hi) tiles to smem as fp16 ----
        #pragma unroll
        for (int it = 0; it < 8; ++it) {
            int idx = tid + it * NT;          // 0..2047
            int r   = idx >> 5;               // 0..63
            int cc  = (idx & 31) << 2;        // 0..124
            float4 kv = *reinterpret_cast<const float4*>(Kg + (size_t)(k0 + r) * D_DIM + cc);
            __half h0 = __float2half_rn(kv.x), h1 = __float2half_rn(kv.y);
            __half h2 = __float2half_rn(kv.z), h3 = __float2half_rn(kv.w);
            __half e0 = __float2half_rn(kv.x - __half2float(h0));
            __half e1 = __float2half_rn(kv.y - __half2float(h1));
            __half e2 = __float2half_rn(kv.z - __half2float(h2));
            __half e3 = __float2half_rn(kv.w - __half2float(h3));
            *reinterpret_cast<__half2*>(Kh + r * KST + cc)     = __halves2half2(h0, h1);
            *reinterpret_cast<__half2*>(Kh + r * KST + cc + 2) = __halves2half2(h2, h3);
            *reinterpret_cast<__half2*>(Kl + r * KST + cc)     = __halves2half2(e0, e1);
            *reinterpret_cast<__half2*>(Kl + r * KST + cc + 2) = __halves2half2(e2, e3);
            float4 vv = *reinterpret_cast<const float4*>(Vg + (size_t)(k0 + r) * D_DIM + cc);
            *reinterpret_cast<__half2*>(Vh + r * KST + cc) =
                __halves2half2(__float2half_rn(vv.x), __float2half_rn(vv.y));
            *reinterpret_cast<__half2*>(Vh + r * KST + cc + 2) =
                __halves2half2(__float2half_rn(vv.z), __float2half_rn(vv.w));
        }
        __syncthreads();

        // ---- S = Q @ K^T, split into qh*kh + ql*kh + qh*kl ----
        float sacc[8][4];
        #pragma unroll
        for (int n = 0; n < 8; ++n)
            #pragma unroll
            for (int j = 0; j < 4; ++j) sacc[n][j] = 0.0f;

        #pragma unroll
        for (int n = 0; n < 8; ++n) {
            const uint32_t rowoff = (uint32_t)(n * 8 * 272);
            #pragma unroll
            for (int dp = 0; dp < 4; ++dp) {
                uint32_t bh0, bh1, bh2, bh3, bl0, bl1, bl2, bl3;
                ldsm_x4(bh0, bh1, bh2, bh3, kh_base + rowoff + (uint32_t)(dp * 64));
                ldsm_x4(bl0, bl1, bl2, bl3, kl_base + rowoff + (uint32_t)(dp * 64));
                mma_f16(sacc[n], qh[2 * dp],     bh0, bh1);
                mma_f16(sacc[n], qh[2 * dp + 1], bh2, bh3);
                mma_f16(sacc[n], ql[2 * dp],     bh0, bh1);
                mma_f16(sacc[n], ql[2 * dp + 1], bh2, bh3);
                mma_f16(sacc[n], qh[2 * dp],     bl0, bl1);
                mma_f16(sacc[n], qh[2 * dp + 1], bl2, bl3);
            }
        }

        // ---- online softmax (rows g and g+8 per thread) ----
        float mx0 = -CUDART_INF_F, mx1 = -CUDART_INF_F;
        #pragma unroll
        for (int n = 0; n < 8; ++n) {
            sacc[n][0] *= inv3; sacc[n][1] *= inv3;
            sacc[n][2] *= inv3; sacc[n][3] *= inv3;
            mx0 = fmaxf(mx0, fmaxf(sacc[n][0], sacc[n][1]));
            mx1 = fmaxf(mx1, fmaxf(sacc[n][2], sacc[n][3]));
        }
        mx0 = fmaxf(mx0, __shfl_xor_sync(0xffffffffu, mx0, 1));
        mx0 = fmaxf(mx0, __shfl_xor_sync(0xffffffffu, mx0, 2));
        mx1 = fmaxf(mx1, __shfl_xor_sync(0xffffffffu, mx1, 1));
        mx1 = fmaxf(mx1, __shfl_xor_sync(0xffffffffu, mx1, 2));
        float mn0 = fmaxf(m0, mx0), mn1 = fmaxf(m1, mx1);
        float sc0 = __expf(m0 - mn0), sc1 = __expf(m1 - mn1);
        m0 = mn0; m1 = mn1;
        float rs0 = 0.0f, rs1 = 0.0f;
        #pragma unroll
        for (int n = 0; n < 8; ++n) {
            sacc[n][0] = __expf(sacc[n][0] - mn0);
            sacc[n][1] = __expf(sacc[n][1] - mn0);
            sacc[n][2] = __expf(sacc[n][2] - mn1);
            sacc[n][3] = __expf(sacc[n][3] - mn1);
            rs0 += sacc[n][0] + sacc[n][1];
            rs1 += sacc[n][2] + sacc[n][3];
        }
        rs0 += __shfl_xor_sync(0xffffffffu, rs0, 1);
        rs0 += __shfl_xor_sync(0xffffffffu, rs0, 2);
        rs1 += __shfl_xor_sync(0xffffffffu, rs1, 1);
        rs1 += __shfl_xor_sync(0xffffffffu, rs1, 2);
        l0 = l0 * sc0 + rs0;
        l1 = l1 * sc1 + rs1;
        #pragma unroll
        for (int i = 0; i < 16; ++i) {
            oacc[i][0] *= sc0; oacc[i][1] *= sc0;
            oacc[i][2] *= sc1; oacc[i][3] *= sc1;
        }

        // ---- threefry dropout mask + pack P to fp16 A-fragments ----
        uint32_t pfr[8][2];
        const unsigned gt = gbase + (unsigned)k0;
        #pragma unroll
        for (int n = 0; n < 8; ++n) {
            unsigned gi = gt + (unsigned)(8 * n);
            unsigned b00 = threefry_bits_part(gi);
            unsigned b01 = threefry_bits_part(gi + 1u);
            unsigned b10 = threefry_bits_part(gi + 16384u);
            unsigned b11 = threefry_bits_part(gi + 16385u);
            float p00 = ((int)b00 >= 0) ? sacc[n][0] : 0.0f;
            float p01 = ((int)b01 >= 0) ? sacc[n][1] : 0.0f;
            float p10 = ((int)b10 >= 0) ? sacc[n][2] : 0.0f;
            float p11 = ((int)b11 >= 0) ? sacc[n][3] : 0.0f;
            pfr[n][0] = packh2(__float2half_rn(p00), __float2half_rn(p01));
            pfr[n][1] = packh2(__float2half_rn(p10), __float2half_rn(p11));
        }

        // ---- O += P @ V ----
        #pragma unroll
        for (int kk = 0; kk < 4; ++kk) {
            uint32_t a[4] = { pfr[2 * kk][0], pfr[2 * kk][1],
                              pfr[2 * kk + 1][0], pfr[2 * kk + 1][1] };
            const uint32_t kkoff = (uint32_t)(kk * 16 * 272);
            #pragma unroll
            for (int np = 0; np < 8; ++np) {
                uint32_t b0, b1, b2, b3;
                ldsm_x4_t(b0, b1, b2, b3, vh_base + kkoff + (uint32_t)(np * 32));
                mma_f16(oacc[2 * np],     a, b0, b1);
                mma_f16(oacc[2 * np + 1], a, b2, b3);
            }
        }
    }

    // ---- epilogue: out = 2*o/l + residual(x2) ----
    const float il0 = 2.0f / l0;
    const float il1 = 2.0f / l1;
    #pragma unroll
    for (int np = 0; np < 16; ++np) {
        int col = 8 * np + 2 * c;
        const float2 r0 = *reinterpret_cast<const float2*>(R + (size_t)qrow * D_DIM + col);
        const float2 r1 = *reinterpret_cast<const float2*>(R + (size_t)(qrow + 8) * D_DIM + col);
        float2 w0, w1;
        w0.x = fmaf(oacc[np][0], il0, r0.x);
        w0.y = fmaf(oacc[np][1], il0, r0.y);
        w1.x = fmaf(oacc[np][2], il1, r1.x);
        w1.y = fmaf(oacc[np][3], il1, r1.y);
        *reinterpret_cast<float2*>(O + (size_t)qrow * D_DIM + col) = w0;
        *reinterpret_cast<float2*>(O + (size_t)(qrow + 8) * D_DIM + col) = w1;
    }
}

extern "C" void kernel_launch(void* const* d_in, const int* in_sizes, int n_in,
                              void* d_out, int out_size) {
    const float* x1 = (const float*)d_in[0];   // [2,16,2048,128]
    const float* x2 = (const float*)d_in[1];   // [2,16,2048,128]
    const float* x3 = (const float*)d_in[2];   // [2,16,1,1]
    float* out = (float*)d_out;

    (void)in_sizes; (void)n_in; (void)out_size;

    cudaFuncSetAttribute(attn_mma_kernel,
                         cudaFuncAttributeMaxDynamicSharedMemorySize, SMEM_BYTES);

    dim3 grid(S_LEN / BM, 32);
    attn_mma_kernel<<<grid, NT, SMEM_BYTES>>>(x1, x2, x3, out);
}

// round 4
// speedup vs baseline: 2.7088x; 1.0282x over previous
#include <cuda_runtime.h>
#include <cuda_fp16.h>
#include <math_constants.h>
#include <cstdint>

// Fused attention via mma.sync (HMMA fp16, fp32 acc), round 4:
//  - prologue kernel pre-converts K -> (Kh, Kl) fp16 split and V -> Vh fp16
//    into __device__ scratch (removes per-tile conversion ALU: 16x redundant).
//  - main kernel double-buffers fp16 tiles with cp.async (gmem latency hidden).
//  - threefry mask bits computed up-front per tile (packed, 1 reg) so int ALU
//    interleaves with tensor ops.
// Math identical to round-3 passing kernel. rel_err ~1.5e-4 expected.

#define S_LEN 2048
#define D_DIM 128
#define BM 128
#define BN 64
#define NT 256
#define NELEM (2 * 16 * S_LEN * D_DIM)      // 8,388,608 elements per tensor

#define KST 136                              // halves per smem row (128+8 pad)
#define TILE_HALVES (64 * KST)               // 8704 halves = 17408 B per array
#define STAGE_HALVES (3 * TILE_HALVES)       // Kh, Kl, Vh
#define SMEM_HALVES (2 * STAGE_HALVES)       // double buffered
#define SMEM_BYTES (SMEM_HALVES * 2)         // 104448 B
#define KH_OFF 0
#define KL_OFF TILE_HALVES
#define VH_OFF (2 * TILE_HALVES)

// __device__ scratch (sanctioned alternative to cudaMalloc)
__device__ __half g_Kh[NELEM];
__device__ __half g_Kl[NELEM];
__device__ __half g_Vh[NELEM];

// ---------------- prologue: fp32 -> fp16 hi/lo conversion ----------------
__global__ void __launch_bounds__(256, 4)
convert_kernel(const float* __restrict__ x1, const float* __restrict__ x2)
{
    int stride = gridDim.x * blockDim.x;
    for (int i = blockIdx.x * blockDim.x + threadIdx.x; i < NELEM / 4; i += stride) {
        float4 k = reinterpret_cast<const float4*>(x2)[i];
        float4 v = reinterpret_cast<const float4*>(x1)[i];
        __half h0 = __float2half_rn(k.x), h1 = __float2half_rn(k.y);
        __half h2 = __float2half_rn(k.z), h3 = __float2half_rn(k.w);
        __half e0 = __float2half_rn(k.x - __half2float(h0));
        __half e1 = __float2half_rn(k.y - __half2float(h1));
        __half e2 = __float2half_rn(k.z - __half2float(h2));
        __half e3 = __float2half_rn(k.w - __half2float(h3));
        __half2 kh01 = __halves2half2(h0, h1), kh23 = __halves2half2(h2, h3);
        __half2 kl01 = __halves2half2(e0, e1), kl23 = __halves2half2(e2, e3);
        __half2 vh01 = __halves2half2(__float2half_rn(v.x), __float2half_rn(v.y));
        __half2 vh23 = __halves2half2(__float2half_rn(v.z), __float2half_rn(v.w));
        reinterpret_cast<__half2*>(g_Kh)[2 * i]     = kh01;
        reinterpret_cast<__half2*>(g_Kh)[2 * i + 1] = kh23;
        reinterpret_cast<__half2*>(g_Kl)[2 * i]     = kl01;
        reinterpret_cast<__half2*>(g_Kl)[2 * i + 1] = kl23;
        reinterpret_cast<__half2*>(g_Vh)[2 * i]     = vh01;
        reinterpret_cast<__half2*>(g_Vh)[2 * i + 1] = vh23;
    }
}

// ---------------- threefry (JAX partitionable, key=(0,42)) ----------------
__device__ __forceinline__ unsigned tf_rotl(unsigned x, int r) {
    return __funnelshift_l(x, x, r);
}
__device__ __forceinline__ unsigned threefry_bits_part(unsigned g) {
    const unsigned ks1 = 42u;
    const unsigned ks2 = 0x1BD11BDAu ^ 42u;
    unsigned x0 = 0u;
    unsigned x1 = g + ks1;
#define TF_ROUND(r) { x0 += x1; x1 = tf_rotl(x1, (r)) ^ x0; }
    TF_ROUND(13) TF_ROUND(15) TF_ROUND(26) TF_ROUND(6)
    x0 += ks1; x1 += ks2 + 1u;
    TF_ROUND(17) TF_ROUND(29) TF_ROUND(16) TF_ROUND(24)
    x0 += ks2; x1 += 0u + 2u;
    TF_ROUND(13) TF_ROUND(15) TF_ROUND(26) TF_ROUND(6)
    x0 += 0u; x1 += ks1 + 3u;
    TF_ROUND(17) TF_ROUND(29) TF_ROUND(16) TF_ROUND(24)
    x0 += ks1; x1 += ks2 + 4u;
    TF_ROUND(13) TF_ROUND(15) TF_ROUND(26) TF_ROUND(6)
    x0 += ks2; x1 += 0u + 5u;
#undef TF_ROUND
    return x0 ^ x1;
}

__device__ __forceinline__ uint32_t packh2(__half a, __half b) {
    __half2 h = __halves2half2(a, b);
    return *reinterpret_cast<uint32_t*>(&h);
}
__device__ __forceinline__ void mma_f16(float c[4], const uint32_t a[4],
                                        uint32_t b0, uint32_t b1) {
    asm volatile(
        "mma.sync.aligned.m16n8k16.row.col.f32.f16.f16.f32 "
        "{%0,%1,%2,%3}, {%4,%5,%6,%7}, {%8,%9}, {%0,%1,%2,%3};\n"
        : "+f"(c[0]), "+f"(c[1]), "+f"(c[2]), "+f"(c[3])
        : "r"(a[0]), "r"(a[1]), "r"(a[2]), "r"(a[3]), "r"(b0), "r"(b1));
}
__device__ __forceinline__ void ldsm_x4(uint32_t& r0, uint32_t& r1,
                                        uint32_t& r2, uint32_t& r3, uint32_t addr) {
    asm volatile("ldmatrix.sync.aligned.m8n8.x4.shared.b16 {%0,%1,%2,%3}, [%4];"
                 : "=r"(r0), "=r"(r1), "=r"(r2), "=r"(r3) : "r"(addr));
}
__device__ __forceinline__ void ldsm_x4_t(uint32_t& r0, uint32_t& r1,
                                          uint32_t& r2, uint32_t& r3, uint32_t addr) {
    asm volatile("ldmatrix.sync.aligned.m8n8.x4.trans.shared.b16 {%0,%1,%2,%3}, [%4];"
                 : "=r"(r0), "=r"(r1), "=r"(r2), "=r"(r3) : "r"(addr));
}
__device__ __forceinline__ void cp_async16(uint32_t dst_smem, const void* src) {
    asm volatile("cp.async.cg.shared.global [%0], [%1], 16;"
                 :: "r"(dst_smem), "l"(src));
}
__device__ __forceinline__ void cp_commit() {
    asm volatile("cp.async.commit_group;");
}
template <int N>
__device__ __forceinline__ void cp_wait() {
    asm volatile("cp.async.wait_group %0;" :: "n"(N));
}

// issue cp.async for one k-tile (64 rows x 128 halves per array, 3 arrays)
__device__ __forceinline__ void stage_tile(uint32_t smem_stage_b, int bh, int k0, int tid)
{
    const size_t base = (size_t)bh * (S_LEN * D_DIM) + (size_t)k0 * D_DIM;
    const __half* srcs[3] = { g_Kh + base, g_Kl + base, g_Vh + base };
    #pragma unroll
    for (int it = 0; it < 12; ++it) {
        int id  = tid + it * NT;         // 0..3071
        int arr = id >> 10;              // /1024
        int rem = id & 1023;
        int row = rem >> 4;              // 0..63
        int col = rem & 15;              // 16B chunk within row
        uint32_t dst = smem_stage_b + (uint32_t)(arr * (TILE_HALVES * 2)
                                               + row * (KST * 2) + col * 16);
        cp_async16(dst, srcs[arr] + (size_t)row * D_DIM + col * 8);
    }
}

__global__ void __launch_bounds__(NT, 1)
attn_mma_kernel(const float* __restrict__ x1,
                const float* __restrict__ x2,
                const float* __restrict__ x3,
                float* __restrict__ out)
{
    extern __shared__ __half smh[];

    const int tid  = threadIdx.x;
    const int warp = tid >> 5;
    const int lane = tid & 31;
    const int g    = lane >> 2;
    const int c    = lane & 3;
    const int bh   = blockIdx.y;
    const int q0   = blockIdx.x * BM;
    const int qrow = q0 + warp * 16 + g;

    const float* Q = x1 + (size_t)bh * (S_LEN * D_DIM);
    const float* R = x2 + (size_t)bh * (S_LEN * D_DIM);   // residual
    float* O = out + (size_t)bh * (S_LEN * D_DIM);
    const float inv3 = 1.0f / x3[bh];

    // ---- preload tile 0 ----
    const uint32_t smem_u32 = (uint32_t)__cvta_generic_to_shared(smh);
    stage_tile(smem_u32, bh, 0, tid);
    cp_commit();

    // ---- Q fragments resident (hi + lo split) ----
    uint32_t qh[8][4], ql[8][4];
    #pragma unroll
    for (int t = 0; t < 8; ++t) {
        #pragma unroll
        for (int p = 0; p < 4; ++p) {
            int row = qrow + (p & 1) * 8;
            int col = 16 * t + (p >> 1) * 8 + 2 * c;
            float2 v = *reinterpret_cast<const float2*>(Q + (size_t)row * D_DIM + col);
            __half hx = __float2half_rn(v.x), hy = __float2half_rn(v.y);
            __half lx = __float2half_rn(v.x - __half2float(hx));
            __half ly = __float2half_rn(v.y - __half2float(hy));
            qh[t][p] = packh2(hx, hy);
            ql[t][p] = packh2(lx, ly);
        }
    }

    float oacc[16][4];
    #pragma unroll
    for (int i = 0; i < 16; ++i)
        #pragma unroll
        for (int j = 0; j < 4; ++j) oacc[i][j] = 0.0f;
    float m0 = -CUDART_INF_F, m1 = -CUDART_INF_F;
    float l0 = 0.0f, l1 = 0.0f;

    // ldmatrix per-lane address components (within a stage)
    const int lr  = lane & 7;
    const int seg = lane >> 3;
    const uint32_t k_lane_off = (uint32_t)(lr * 272 + ((seg & 1) * 8 + (seg >> 1) * 16) * 2);
    const uint32_t v_lane_off = (uint32_t)(((seg & 1) * 8 + lr) * 272 + ((seg >> 1) * 8) * 2);
    const uint32_t kh_base0 = smem_u32 + k_lane_off;
    const uint32_t kl_base0 = smem_u32 + (uint32_t)(KL_OFF * 2) + k_lane_off;
    const uint32_t vh_base0 = smem_u32 + (uint32_t)(VH_OFF * 2) + v_lane_off;

    const unsigned gbase = ((unsigned)bh * 2048u + (unsigned)qrow) * 2048u + (unsigned)(2 * c);

    for (int kt = 0; kt < S_LEN / BN; ++kt) {
        const int k0 = kt * BN;
        const uint32_t cur = (uint32_t)(kt & 1) * (STAGE_HALVES * 2);
        const uint32_t nxt = (uint32_t)((kt + 1) & 1) * (STAGE_HALVES * 2);

        __syncthreads();   // everyone done consuming the buffer we overwrite next
        if (kt + 1 < S_LEN / BN) {
            stage_tile(smem_u32 + nxt, bh, k0 + BN, tid);
            cp_commit();
            cp_wait<1>();  // tile kt arrived
        } else {
            cp_wait<0>();
        }

        // ---- threefry mask bits for this tile (packed; interleaves with MMAs) ----
        uint32_t keepbits = 0u;
        {
            const unsigned gt = gbase + (unsigned)k0;
            #pragma unroll
            for (int n = 0; n < 8; ++n) {
                unsigned gi = gt + (unsigned)(8 * n);
                unsigned b00 = threefry_bits_part(gi);
                unsigned b01 = threefry_bits_part(gi + 1u);
                unsigned b10 = threefry_bits_part(gi + 16384u);
                unsigned b11 = threefry_bits_part(gi + 16385u);
                keepbits |= ((~b00) >> 31) << (4 * n + 0);
                keepbits |= ((~b01) >> 31) << (4 * n + 1);
                keepbits |= ((~b10) >> 31) << (4 * n + 2);
                keepbits |= ((~b11) >> 31) << (4 * n + 3);
            }
        }

        __syncthreads();   // cp.async data visible to all warps

        const uint32_t kh_base = kh_base0 + cur;
        const uint32_t kl_base = kl_base0 + cur;
        const uint32_t vh_base = vh_base0 + cur;

        // ---- S = Q @ K^T (qh*kh + ql*kh + qh*kl) ----
        float sacc[8][4];
        #pragma unroll
        for (int n = 0; n < 8; ++n)
            #pragma unroll
            for (int j = 0; j < 4; ++j) sacc[n][j] = 0.0f;

        #pragma unroll
        for (int n = 0; n < 8; ++n) {
            const uint32_t rowoff = (uint32_t)(n * 8 * 272);
            #pragma unroll
            for (int dp = 0; dp < 4; ++dp) {
                uint32_t bh0, bh1, bh2, bh3, bl0, bl1, bl2, bl3;
                ldsm_x4(bh0, bh1, bh2, bh3, kh_base + rowoff + (uint32_t)(dp * 64));
                ldsm_x4(bl0, bl1, bl2, bl3, kl_base + rowoff + (uint32_t)(dp * 64));
                mma_f16(sacc[n], qh[2 * dp],     bh0, bh1);
                mma_f16(sacc[n], qh[2 * dp + 1], bh2, bh3);
                mma_f16(sacc[n], ql[2 * dp],     bh0, bh1);
                mma_f16(sacc[n], ql[2 * dp + 1], bh2, bh3);
                mma_f16(sacc[n], qh[2 * dp],     bl0, bl1);
                mma_f16(sacc[n], qh[2 * dp + 1], bl2, bl3);
            }
        }

        // ---- online softmax ----
        float mx0 = -CUDART_INF_F, mx1 = -CUDART_INF_F;
        #pragma unroll
        for (int n = 0; n < 8; ++n) {
            sacc[n][0] *= inv3; sacc[n][1] *= inv3;
            sacc[n][2] *= inv3; sacc[n][3] *= inv3;
            mx0 = fmaxf(mx0, fmaxf(sacc[n][0], sacc[n][1]));
            mx1 = fmaxf(mx1, fmaxf(sacc[n][2], sacc[n][3]));
        }
        mx0 = fmaxf(mx0, __shfl_xor_sync(0xffffffffu, mx0, 1));
        mx0 = fmaxf(mx0, __shfl_xor_sync(0xffffffffu, mx0, 2));
        mx1 = fmaxf(mx1, __shfl_xor_sync(0xffffffffu, mx1, 1));
        mx1 = fmaxf(mx1, __shfl_xor_sync(0xffffffffu, mx1, 2));
        float mn0 = fmaxf(m0, mx0), mn1 = fmaxf(m1, mx1);
        float sc0 = __expf(m0 - mn0), sc1 = __expf(m1 - mn1);
        m0 = mn0; m1 = mn1;
        float rs0 = 0.0f, rs1 = 0.0f;
        #pragma unroll
        for (int n = 0; n < 8; ++n) {
            sacc[n][0] = __expf(sacc[n][0] - mn0);
            sacc[n][1] = __expf(sacc[n][1] - mn0);
            sacc[n][2] = __expf(sacc[n][2] - mn1);
            sacc[n][3] = __expf(sacc[n][3] - mn1);
            rs0 += sacc[n][0] + sacc[n][1];
            rs1 += sacc[n][2] + sacc[n][3];
        }
        rs0 += __shfl_xor_sync(0xffffffffu, rs0, 1);
        rs0 += __shfl_xor_sync(0xffffffffu, rs0, 2);
        rs1 += __shfl_xor_sync(0xffffffffu, rs1, 1);
        rs1 += __shfl_xor_sync(0xffffffffu, rs1, 2);
        l0 = l0 * sc0 + rs0;
        l1 = l1 * sc1 + rs1;
        #pragma unroll
        for (int i = 0; i < 16; ++i) {
            oacc[i][0] *= sc0; oacc[i][1] *= sc0;
            oacc[i][2] *= sc1; oacc[i][3] *= sc1;
        }

        // ---- apply mask bits + pack P to fp16 A-fragments ----
        uint32_t pfr[8][2];
        #pragma unroll
        for (int n = 0; n < 8; ++n) {
            float p00 = ((keepbits >> (4 * n + 0)) & 1u) ? sacc[n][0] : 0.0f;
            float p01 = ((keepbits >> (4 * n + 1)) & 1u) ? sacc[n][1] : 0.0f;
            float p10 = ((keepbits >> (4 * n + 2)) & 1u) ? sacc[n][2] : 0.0f;
            float p11 = ((keepbits >> (4 * n + 3)) & 1u) ? sacc[n][3] : 0.0f;
            pfr[n][0] = packh2(__float2half_rn(p00), __float2half_rn(p01));
            pfr[n][1] = packh2(__float2half_rn(p10), __float2half_rn(p11));
        }

        // ---- O += P @ V ----
        #pragma unroll
        for (int kk = 0; kk < 4; ++kk) {
            uint32_t a[4] = { pfr[2 * kk][0], pfr[2 * kk][1],
                              pfr[2 * kk + 1][0], pfr[2 * kk + 1][1] };
            const uint32_t kkoff = (uint32_t)(kk * 16 * 272);
            #pragma unroll
            for (int np = 0; np < 8; ++np) {
                uint32_t b0, b1, b2, b3;
                ldsm_x4_t(b0, b1, b2, b3, vh_base + kkoff + (uint32_t)(np * 32));
                mma_f16(oacc[2 * np],     a, b0, b1);
                mma_f16(oacc[2 * np + 1], a, b2, b3);
            }
        }
    }

    // ---- epilogue: out = 2*o/l + residual(x2) ----
    const float il0 = 2.0f / l0;
    const float il1 = 2.0f / l1;
    #pragma unroll
    for (int np = 0; np < 16; ++np) {
        int col = 8 * np + 2 * c;
        const float2 r0 = *reinterpret_cast<const float2*>(R + (size_t)qrow * D_DIM + col);
        const float2 r1 = *reinterpret_cast<const float2*>(R + (size_t)(qrow + 8) * D_DIM + col);
        float2 w0, w1;
        w0.x = fmaf(oacc[np][0], il0, r0.x);
        w0.y = fmaf(oacc[np][1], il0, r0.y);
        w1.x = fmaf(oacc[np][2], il1, r1.x);
        w1.y = fmaf(oacc[np][3], il1, r1.y);
        *reinterpret_cast<float2*>(O + (size_t)qrow * D_DIM + col) = w0;
        *reinterpret_cast<float2*>(O + (size_t)(qrow + 8) * D_DIM + col) = w1;
    }
}

extern "C" void kernel_launch(void* const* d_in, const int* in_sizes, int n_in,
                              void* d_out, int out_size) {
    const float* x1 = (const float*)d_in[0];
    const float* x2 = (const float*)d_in[1];
    const float* x3 = (const float*)d_in[2];
    float* out = (float*)d_out;
    (void)in_sizes; (void)n_in; (void)out_size;

    cudaFuncSetAttribute(attn_mma_kernel,
                         cudaFuncAttributeMaxDynamicSharedMemorySize, SMEM_BYTES);

    convert_kernel<<<1024, 256>>>(x1, x2);
    dim3 grid(S_LEN / BM, 32);
    attn_mma_kernel<<<grid, NT, SMEM_BYTES>>>(x1, x2, x3, out);
}